// round 1
// baseline (speedup 1.0000x reference)
#include <cuda_runtime.h>
#include <math.h>

#define B_  2
#define S_  2048
#define D_  2048
#define H_  16
#define HD_ 128
#define M_  (B_*S_)          // 4096

#define SCALE_ 0.08838834764831845f   // 1/sqrt(128)

// -------- scratch (allocation-free rule: __device__ globals) --------
static __device__ float g_q [B_*H_*S_*HD_];   // 32 MB each
static __device__ float g_k [B_*H_*S_*HD_];
static __device__ float g_v [B_*H_*S_*HD_];
static __device__ float g_ao[B_*S_*D_];

// =====================================================================
// NT GEMM: C[m,n] = sum_k A[m,k] * W[n,k]
// 128x128 tile, BK=16, 256 threads, 8x8 microtile (split 4+4 rows/cols)
// scatter=1: z selects Wq/Wk/Wv, writes [B,H,S,HD] layout into g_q/g_k/g_v
// scatter=0: A := g_ao, W := W0 (Wo), plain row-major write to Cout
// =====================================================================
__global__ __launch_bounds__(256, 2) void gemm_nt(
    const float* __restrict__ A,
    const float* __restrict__ W0, const float* __restrict__ W1,
    const float* __restrict__ W2,
    float* __restrict__ Cout, int scatter)
{
    __shared__ float As[16*128];
    __shared__ float Bs[16*128];

    const int tid = threadIdx.x;
    const int tx  = tid & 15;
    const int ty  = tid >> 4;
    const int m0  = blockIdx.y * 128;
    const int n0  = blockIdx.x * 128;

    const float* W = W0;
    float* outq = nullptr;
    const float* Ap = A;
    if (scatter) {
        if (blockIdx.z == 1)      W = W1;
        else if (blockIdx.z == 2) W = W2;
        outq = (blockIdx.z == 0) ? g_q : (blockIdx.z == 1) ? g_k : g_v;
    } else {
        Ap = g_ao;
    }

    float acc[8][8];
#pragma unroll
    for (int i = 0; i < 8; i++)
#pragma unroll
        for (int j = 0; j < 8; j++) acc[i][j] = 0.f;

    for (int k0 = 0; k0 < D_; k0 += 16) {
#pragma unroll
        for (int i = 0; i < 2; i++) {
            int pos = (i << 8) + tid;          // 0..511
            int row = pos >> 2;                // 0..127
            int kc  = (pos & 3) << 2;          // 0,4,8,12
            float4 va = *(const float4*)(Ap + (size_t)(m0 + row) * D_ + k0 + kc);
            float4 vb = *(const float4*)(W  + (size_t)(n0 + row) * D_ + k0 + kc);
            As[(kc+0)*128 + row] = va.x; As[(kc+1)*128 + row] = va.y;
            As[(kc+2)*128 + row] = va.z; As[(kc+3)*128 + row] = va.w;
            Bs[(kc+0)*128 + row] = vb.x; Bs[(kc+1)*128 + row] = vb.y;
            Bs[(kc+2)*128 + row] = vb.z; Bs[(kc+3)*128 + row] = vb.w;
        }
        __syncthreads();

#pragma unroll
        for (int k = 0; k < 16; k++) {
            float a[8], b[8];
            *(float4*)&a[0] = *(float4*)&As[k*128 + ty*4];
            *(float4*)&a[4] = *(float4*)&As[k*128 + 64 + ty*4];
            *(float4*)&b[0] = *(float4*)&Bs[k*128 + tx*4];
            *(float4*)&b[4] = *(float4*)&Bs[k*128 + 64 + tx*4];
#pragma unroll
            for (int i = 0; i < 8; i++)
#pragma unroll
                for (int j = 0; j < 8; j++)
                    acc[i][j] += a[i] * b[j];
        }
        __syncthreads();
    }

    // epilogue
#pragma unroll
    for (int ri = 0; ri < 2; ri++)
#pragma unroll
    for (int ii = 0; ii < 4; ii++) {
        int r = m0 + ri*64 + ty*4 + ii;
#pragma unroll
        for (int cj = 0; cj < 2; cj++) {
            int c = cj*64 + tx*4;
            float4 v = make_float4(acc[ri*4+ii][cj*4+0], acc[ri*4+ii][cj*4+1],
                                   acc[ri*4+ii][cj*4+2], acc[ri*4+ii][cj*4+3]);
            if (!scatter) {
                *(float4*)(Cout + (size_t)r * D_ + n0 + c) = v;
            } else {
                int h  = n0 >> 7;            // tile covers exactly one head
                int bb = r >> 11;
                int s  = r & (S_ - 1);
                *(float4*)(outq + ((size_t)(bb*H_ + h) * S_ + s) * HD_ + c) = v;
            }
        }
    }
}

// =====================================================================
// RoPE in-place on g_q and g_k. One thread per (b,h,s,d<64) pair.
// =====================================================================
__global__ void rope_kernel(const float* __restrict__ cosT,
                            const float* __restrict__ sinT)
{
    int idx = blockIdx.x * blockDim.x + threadIdx.x;   // over B*H*S*64
    int d  = idx & 63;
    int s  = (idx >> 6) & (S_ - 1);
    int bh = idx >> 17;
    size_t base = ((size_t)bh * S_ + s) * HD_;
    float c  = cosT[s*HD_ + d];
    float sn = sinT[s*HD_ + d];

    float q1 = g_q[base + d], q2 = g_q[base + d + 64];
    g_q[base + d]      = q1*c - q2*sn;
    g_q[base + d + 64] = q2*c + q1*sn;

    float k1 = g_k[base + d], k2 = g_k[base + d + 64];
    g_k[base + d]      = k1*c - k2*sn;
    g_k[base + d + 64] = k2*c + k1*sn;
}

// =====================================================================
// Flash attention, causal. 64 q-rows x 64 k-cols per iteration, HD=128.
// 256 threads: 16x16 grid; score microtile rows ty+16i / cols tx+16j
// (stride-16 layout keeps LDS.128 at the 2-way minimum with row pad 132).
// Output microtile: rows ty+16i, cols tx*4 and 64+tx*4.
// =====================================================================
#define QSTR 132
#define PSTR 68
#define ATT_SMEM ((3*64*QSTR + 64*PSTR) * 4)   // 118784 bytes

__global__ __launch_bounds__(256, 1) void attn_kernel()
{
    extern __shared__ float sm[];
    float* Qs = sm;
    float* Ks = sm + 64*QSTR;
    float* Vs = sm + 2*64*QSTR;
    float* Ps = sm + 3*64*QSTR;

    const int tid = threadIdx.x;
    const int tx  = tid & 15;
    const int ty  = tid >> 4;
    const int qb  = (int)(gridDim.x - 1 - blockIdx.x);  // big blocks first
    const int bh  = blockIdx.y;
    const int q0  = qb * 64;

    const float* qp = g_q + (size_t)bh * S_ * HD_;
    const float* kp = g_k + (size_t)bh * S_ * HD_;
    const float* vp = g_v + (size_t)bh * S_ * HD_;

    // load Q tile (64 x 128)
#pragma unroll
    for (int i = 0; i < 8; i++) {
        int pos = i*256 + tid;
        int row = pos >> 5;
        int kc  = (pos & 31) << 2;
        *(float4*)&Qs[row*QSTR + kc] =
            *(const float4*)&qp[(size_t)(q0 + row) * HD_ + kc];
    }

    float m_i[4], l_i[4], o_[4][8];
#pragma unroll
    for (int i = 0; i < 4; i++) {
        m_i[i] = -INFINITY; l_i[i] = 0.f;
#pragma unroll
        for (int c = 0; c < 8; c++) o_[i][c] = 0.f;
    }

    for (int kb = 0; kb <= q0; kb += 64) {
        __syncthreads();   // previous iter's Ks/Vs/Ps fully consumed
#pragma unroll
        for (int i = 0; i < 8; i++) {
            int pos = i*256 + tid;
            int row = pos >> 5;
            int kc  = (pos & 31) << 2;
            *(float4*)&Ks[row*QSTR + kc] =
                *(const float4*)&kp[(size_t)(kb + row) * HD_ + kc];
            *(float4*)&Vs[row*QSTR + kc] =
                *(const float4*)&vp[(size_t)(kb + row) * HD_ + kc];
        }
        __syncthreads();

        // ---- scores: rs[i][j] = q(ty+16i) . k(tx+16j) ----
        float rs[4][4];
#pragma unroll
        for (int i = 0; i < 4; i++)
#pragma unroll
            for (int j = 0; j < 4; j++) rs[i][j] = 0.f;

#pragma unroll 8
        for (int kk = 0; kk < HD_; kk += 4) {
            float4 q4[4], k4[4];
#pragma unroll
            for (int i = 0; i < 4; i++)
                q4[i] = *(float4*)&Qs[(ty + 16*i)*QSTR + kk];
#pragma unroll
            for (int j = 0; j < 4; j++)
                k4[j] = *(float4*)&Ks[(tx + 16*j)*QSTR + kk];
#pragma unroll
            for (int i = 0; i < 4; i++)
#pragma unroll
                for (int j = 0; j < 4; j++) {
                    rs[i][j] += q4[i].x*k4[j].x;
                    rs[i][j] += q4[i].y*k4[j].y;
                    rs[i][j] += q4[i].z*k4[j].z;
                    rs[i][j] += q4[i].w*k4[j].w;
                }
        }

        const bool diag = (kb == q0);
#pragma unroll
        for (int i = 0; i < 4; i++) {
            int r = ty + 16*i;
            float mx = -INFINITY;
#pragma unroll
            for (int j = 0; j < 4; j++) {
                float v = rs[i][j] * SCALE_;
                if (diag && (tx + 16*j > r)) v = -INFINITY;
                rs[i][j] = v;
                mx = fmaxf(mx, v);
            }
            // row max across the 16-lane group (contiguous half-warp)
            mx = fmaxf(mx, __shfl_xor_sync(0xffffffffu, mx, 1));
            mx = fmaxf(mx, __shfl_xor_sync(0xffffffffu, mx, 2));
            mx = fmaxf(mx, __shfl_xor_sync(0xffffffffu, mx, 4));
            mx = fmaxf(mx, __shfl_xor_sync(0xffffffffu, mx, 8));

            float mnew = fmaxf(m_i[i], mx);
            float corr = __expf(m_i[i] - mnew);
            m_i[i] = mnew;
            l_i[i] *= corr;
#pragma unroll
            for (int c = 0; c < 8; c++) o_[i][c] *= corr;

            float ps = 0.f;
#pragma unroll
            for (int j = 0; j < 4; j++) {
                float p = __expf(rs[i][j] - mnew);
                Ps[r*PSTR + tx + 16*j] = p;
                ps += p;
            }
            l_i[i] += ps;   // partial over this thread's columns
        }
        __syncthreads();

        // ---- O += P @ V ----
#pragma unroll 4
        for (int j = 0; j < 64; j++) {
            float4 v0 = *(float4*)&Vs[j*QSTR + tx*4];
            float4 v1 = *(float4*)&Vs[j*QSTR + 64 + tx*4];
#pragma unroll
            for (int i = 0; i < 4; i++) {
                float p = Ps[(ty + 16*i)*PSTR + j];
                o_[i][0] += p*v0.x; o_[i][1] += p*v0.y;
                o_[i][2] += p*v0.z; o_[i][3] += p*v0.w;
                o_[i][4] += p*v1.x; o_[i][5] += p*v1.y;
                o_[i][6] += p*v1.z; o_[i][7] += p*v1.w;
            }
        }
    }

    // ---- normalize & write [B,S,H*HD] ----
    const int b = bh >> 4, h = bh & 15;
#pragma unroll
    for (int i = 0; i < 4; i++) {
        float lt = l_i[i];
        lt += __shfl_xor_sync(0xffffffffu, lt, 1);
        lt += __shfl_xor_sync(0xffffffffu, lt, 2);
        lt += __shfl_xor_sync(0xffffffffu, lt, 4);
        lt += __shfl_xor_sync(0xffffffffu, lt, 8);
        float inv = 1.f / lt;
        int s = q0 + ty + 16*i;
        float* op = g_ao + ((size_t)(b*S_ + s)) * D_ + h*HD_;
        float4 w0 = make_float4(o_[i][0]*inv, o_[i][1]*inv, o_[i][2]*inv, o_[i][3]*inv);
        float4 w1 = make_float4(o_[i][4]*inv, o_[i][5]*inv, o_[i][6]*inv, o_[i][7]*inv);
        *(float4*)&op[tx*4]      = w0;
        *(float4*)&op[64 + tx*4] = w1;
    }
}

// =====================================================================
extern "C" void kernel_launch(void* const* d_in, const int* in_sizes, int n_in,
                              void* d_out, int out_size)
{
    (void)in_sizes; (void)n_in; (void)out_size;
    const float* x    = (const float*)d_in[0];
    // d_in[1] = mask: exactly causal, implemented analytically
    const float* cosT = (const float*)d_in[2];
    const float* sinT = (const float*)d_in[3];
    const float* Wq   = (const float*)d_in[4];
    const float* Wk   = (const float*)d_in[5];
    const float* Wv   = (const float*)d_in[6];
    const float* Wo   = (const float*)d_in[7];
    float* out = (float*)d_out;

    cudaFuncSetAttribute(attn_kernel,
        cudaFuncAttributeMaxDynamicSharedMemorySize, ATT_SMEM);

    // 1) fused QKV projection -> [B,H,S,HD]
    dim3 gqkv(D_/128, M_/128, 3);
    gemm_nt<<<gqkv, 256>>>(x, Wq, Wk, Wv, nullptr, 1);

    // 2) RoPE in place on q,k
    rope_kernel<<<(B_*H_*S_*64)/256, 256>>>(cosT, sinT);

    // 3) causal flash attention -> g_ao [B,S,D]
    dim3 gatt(S_/64, B_*H_);
    attn_kernel<<<gatt, 256, ATT_SMEM>>>();

    // 4) output projection
    dim3 go(D_/128, M_/128, 1);
    gemm_nt<<<go, 256>>>(nullptr, Wo, nullptr, nullptr, out, 0);
}

// round 3
// speedup vs baseline: 1.7556x; 1.7556x over previous
#include <cuda_runtime.h>
#include <cuda_bf16.h>
#include <math.h>

#define B_  2
#define S_  2048
#define D_  2048
#define H_  16
#define HD_ 128
#define M_  (B_*S_)          // 4096

#define SCALE_ 0.08838834764831845f   // 1/sqrt(128)

// -------- scratch (allocation-free rule: __device__ globals) --------
static __device__ float g_q [B_*H_*S_*HD_];
static __device__ float g_k [B_*H_*S_*HD_];
static __device__ float g_v [B_*H_*S_*HD_];
static __device__ float g_ao[B_*S_*D_];

// ===================== helpers =========================
__device__ __forceinline__ unsigned smem_u32(const void* p) {
    unsigned a;
    asm("{ .reg .u64 t; cvta.to.shared.u64 t, %1; cvt.u32.u64 %0, t; }"
        : "=r"(a) : "l"(p));
    return a;
}

#define LDSM4(r0,r1,r2,r3,a) \
    asm volatile("ldmatrix.sync.aligned.m8n8.x4.shared.b16 {%0,%1,%2,%3}, [%4];" \
        : "=r"(r0),"=r"(r1),"=r"(r2),"=r"(r3) : "r"(a))

#define MMA16816(d, a0,a1,a2,a3, b0,b1) \
    asm volatile("mma.sync.aligned.m16n8k16.row.col.f32.bf16.bf16.f32 " \
        "{%0,%1,%2,%3}, {%4,%5,%6,%7}, {%8,%9}, {%0,%1,%2,%3};" \
        : "+f"((d)[0]),"+f"((d)[1]),"+f"((d)[2]),"+f"((d)[3]) \
        : "r"(a0),"r"(a1),"r"(a2),"r"(a3),"r"(b0),"r"(b1))

// fp32 -> (hi, lo) bf16 split, packed 2x2
__device__ __forceinline__ void cvt_split(float4 v, uint2& hi, uint2& lo) {
    unsigned h01, h23;
    asm("cvt.rn.bf16x2.f32 %0, %1, %2;" : "=r"(h01) : "f"(v.y), "f"(v.x));
    asm("cvt.rn.bf16x2.f32 %0, %1, %2;" : "=r"(h23) : "f"(v.w), "f"(v.z));
    float hx = __uint_as_float(h01 << 16), hy = __uint_as_float(h01 & 0xFFFF0000u);
    float hz = __uint_as_float(h23 << 16), hw = __uint_as_float(h23 & 0xFFFF0000u);
    unsigned l01, l23;
    asm("cvt.rn.bf16x2.f32 %0, %1, %2;" : "=r"(l01) : "f"(v.y - hy), "f"(v.x - hx));
    asm("cvt.rn.bf16x2.f32 %0, %1, %2;" : "=r"(l23) : "f"(v.w - hw), "f"(v.z - hz));
    hi.x = h01; hi.y = h23; lo.x = l01; lo.y = l23;
}

// =====================================================================
// Tensor-core (mma.sync bf16) NT GEMM with 2-way split (hh + lh + hl).
// C[m,n] = sum_k A[m,k] * W[n,k]. Tile 128x128x32, 512 thr, dbl-buffered.
// scatter=1: z selects Wq/Wk/Wv, writes [B,H,S,HD] into g_q/g_k/g_v
// scatter=0: A := g_ao, W := W0 (Wo), row-major write to Cout
// =====================================================================
#define GBK 32
#define GNCH (D_/GBK)      // 64
#define RS 40              // bf16 row stride (80B; ldmatrix conflict-free)
#define AH_OFF 0
#define AL_OFF 10240
#define BH_OFF 20480
#define BL_OFF 30720
#define STG_BYTES 40960
#define GSMEM (2*STG_BYTES)   // 81920

__global__ __launch_bounds__(512, 1) void gemm_mma(
    const float* __restrict__ A,
    const float* __restrict__ W0, const float* __restrict__ W1,
    const float* __restrict__ W2,
    float* __restrict__ Cout, int scatter)
{
    extern __shared__ char sm_[];
    const unsigned sbase = smem_u32(sm_);

    const int tid = threadIdx.x;
    const int wid = tid >> 5, lid = tid & 31;
    const int m0 = blockIdx.y * 128;
    const int n0 = blockIdx.x * 128;

    const float* W = W0;
    const float* Ap = A;
    float* outq = nullptr;
    if (scatter) {
        if (blockIdx.z == 1)      W = W1;
        else if (blockIdx.z == 2) W = W2;
        outq = (blockIdx.z == 0) ? g_q : (blockIdx.z == 1) ? g_k : g_v;
    } else {
        Ap = g_ao;
    }

    const int wm = wid >> 2, wn = wid & 3;      // 4x4 warp grid, 32x32 tile

    // per-lane ldmatrix address components (within-region, bf16 units)
    const int arow = wm*32 + (lid & 7) + ((lid & 8) ? 8 : 0);
    const int acol = (lid & 16) ? 8 : 0;
    const unsigned aoff0 = (unsigned)(arow * RS + acol) * 2u;
    const int brow = wn*32 + (lid & 7) + ((lid & 16) ? 8 : 0);
    const int bcol = (lid & 8) ? 8 : 0;
    const unsigned boff0 = (unsigned)(brow * RS + bcol) * 2u;

    // gmem load indexing: pos = tid + i*512; row = pos>>3; q = pos&7
    const int r0i = tid >> 3, q0i = tid & 7;
    const int r1i = (tid + 512) >> 3, q1i = tid & 7;

    float acc[2][4][4];
#pragma unroll
    for (int mt = 0; mt < 2; mt++)
#pragma unroll
        for (int nt = 0; nt < 4; nt++)
#pragma unroll
            for (int e = 0; e < 4; e++) acc[mt][nt][e] = 0.f;

    float4 pa[2], pb[2];

    // ---- prologue: load chunk 0 ----
    pa[0] = *(const float4*)(Ap + (size_t)(m0 + r0i) * D_ + q0i*4);
    pa[1] = *(const float4*)(Ap + (size_t)(m0 + r1i) * D_ + q1i*4);
    pb[0] = *(const float4*)(W  + (size_t)(n0 + r0i) * D_ + q0i*4);
    pb[1] = *(const float4*)(W  + (size_t)(n0 + r1i) * D_ + q1i*4);
    {
        char* st0 = sm_;
        uint2 hi, lo;
        cvt_split(pa[0], hi, lo);
        *(uint2*)(st0 + AH_OFF + r0i*80 + q0i*8) = hi;
        *(uint2*)(st0 + AL_OFF + r0i*80 + q0i*8) = lo;
        cvt_split(pa[1], hi, lo);
        *(uint2*)(st0 + AH_OFF + r1i*80 + q1i*8) = hi;
        *(uint2*)(st0 + AL_OFF + r1i*80 + q1i*8) = lo;
        cvt_split(pb[0], hi, lo);
        *(uint2*)(st0 + BH_OFF + r0i*80 + q0i*8) = hi;
        *(uint2*)(st0 + BL_OFF + r0i*80 + q0i*8) = lo;
        cvt_split(pb[1], hi, lo);
        *(uint2*)(st0 + BH_OFF + r1i*80 + q1i*8) = hi;
        *(uint2*)(st0 + BL_OFF + r1i*80 + q1i*8) = lo;
    }
    __syncthreads();

#pragma unroll 1
    for (int c = 0; c < GNCH; c++) {
        // prefetch next chunk into registers
        if (c + 1 < GNCH) {
            int k0 = (c + 1) * GBK;
            pa[0] = *(const float4*)(Ap + (size_t)(m0 + r0i) * D_ + k0 + q0i*4);
            pa[1] = *(const float4*)(Ap + (size_t)(m0 + r1i) * D_ + k0 + q1i*4);
            pb[0] = *(const float4*)(W  + (size_t)(n0 + r0i) * D_ + k0 + q0i*4);
            pb[1] = *(const float4*)(W  + (size_t)(n0 + r1i) * D_ + k0 + q1i*4);
        }

        // ---- MMA over current buffer ----
        const unsigned sA = sbase + (unsigned)(c & 1) * STG_BYTES;
#pragma unroll
        for (int ks = 0; ks < 2; ks++) {
            const unsigned kso = (unsigned)(ks * 16 * 2);
            unsigned ah[2][4], al[2][4], bb[2][4];
#pragma unroll
            for (int mt = 0; mt < 2; mt++)
                LDSM4(ah[mt][0],ah[mt][1],ah[mt][2],ah[mt][3],
                      sA + AH_OFF + aoff0 + (unsigned)(mt*16*RS*2) + kso);
#pragma unroll
            for (int mt = 0; mt < 2; mt++)
                LDSM4(al[mt][0],al[mt][1],al[mt][2],al[mt][3],
                      sA + AL_OFF + aoff0 + (unsigned)(mt*16*RS*2) + kso);
#pragma unroll
            for (int p = 0; p < 2; p++)
                LDSM4(bb[p][0],bb[p][1],bb[p][2],bb[p][3],
                      sA + BH_OFF + boff0 + (unsigned)(p*16*RS*2) + kso);
            // hh
#pragma unroll
            for (int mt = 0; mt < 2; mt++)
#pragma unroll
                for (int p = 0; p < 2; p++) {
                    MMA16816(acc[mt][2*p],   ah[mt][0],ah[mt][1],ah[mt][2],ah[mt][3], bb[p][0],bb[p][1]);
                    MMA16816(acc[mt][2*p+1], ah[mt][0],ah[mt][1],ah[mt][2],ah[mt][3], bb[p][2],bb[p][3]);
                }
            // lh
#pragma unroll
            for (int mt = 0; mt < 2; mt++)
#pragma unroll
                for (int p = 0; p < 2; p++) {
                    MMA16816(acc[mt][2*p],   al[mt][0],al[mt][1],al[mt][2],al[mt][3], bb[p][0],bb[p][1]);
                    MMA16816(acc[mt][2*p+1], al[mt][0],al[mt][1],al[mt][2],al[mt][3], bb[p][2],bb[p][3]);
                }
            // load B-lo (overwrite bb), hl
#pragma unroll
            for (int p = 0; p < 2; p++)
                LDSM4(bb[p][0],bb[p][1],bb[p][2],bb[p][3],
                      sA + BL_OFF + boff0 + (unsigned)(p*16*RS*2) + kso);
#pragma unroll
            for (int mt = 0; mt < 2; mt++)
#pragma unroll
                for (int p = 0; p < 2; p++) {
                    MMA16816(acc[mt][2*p],   ah[mt][0],ah[mt][1],ah[mt][2],ah[mt][3], bb[p][0],bb[p][1]);
                    MMA16816(acc[mt][2*p+1], ah[mt][0],ah[mt][1],ah[mt][2],ah[mt][3], bb[p][2],bb[p][3]);
                }
        }

        // ---- store prefetched chunk into the other buffer ----
        if (c + 1 < GNCH) {
            char* st = sm_ + ((c + 1) & 1) * STG_BYTES;
            uint2 hi, lo;
            cvt_split(pa[0], hi, lo);
            *(uint2*)(st + AH_OFF + r0i*80 + q0i*8) = hi;
            *(uint2*)(st + AL_OFF + r0i*80 + q0i*8) = lo;
            cvt_split(pa[1], hi, lo);
            *(uint2*)(st + AH_OFF + r1i*80 + q1i*8) = hi;
            *(uint2*)(st + AL_OFF + r1i*80 + q1i*8) = lo;
            cvt_split(pb[0], hi, lo);
            *(uint2*)(st + BH_OFF + r0i*80 + q0i*8) = hi;
            *(uint2*)(st + BL_OFF + r0i*80 + q0i*8) = lo;
            cvt_split(pb[1], hi, lo);
            *(uint2*)(st + BH_OFF + r1i*80 + q1i*8) = hi;
            *(uint2*)(st + BL_OFF + r1i*80 + q1i*8) = lo;
        }
        __syncthreads();
    }

    // ---- epilogue ----
#pragma unroll
    for (int mt = 0; mt < 2; mt++)
#pragma unroll
    for (int nt = 0; nt < 4; nt++) {
        int r  = m0 + wm*32 + mt*16 + (lid >> 2);
        int cc = n0 + wn*32 + nt*8 + (lid & 3)*2;
        if (!scatter) {
            *(float2*)(Cout + (size_t)r * D_ + cc) =
                make_float2(acc[mt][nt][0], acc[mt][nt][1]);
            *(float2*)(Cout + (size_t)(r + 8) * D_ + cc) =
                make_float2(acc[mt][nt][2], acc[mt][nt][3]);
        } else {
            int h = cc >> 7, cd = cc & 127;
            int b1 = r >> 11, s1 = r & (S_ - 1);
            *(float2*)(outq + ((size_t)(b1*H_ + h) * S_ + s1) * HD_ + cd) =
                make_float2(acc[mt][nt][0], acc[mt][nt][1]);
            int r2 = r + 8;
            int b2 = r2 >> 11, s2 = r2 & (S_ - 1);
            *(float2*)(outq + ((size_t)(b2*H_ + h) * S_ + s2) * HD_ + cd) =
                make_float2(acc[mt][nt][2], acc[mt][nt][3]);
        }
    }
}

// =====================================================================
// RoPE in-place on g_q and g_k.
// =====================================================================
__global__ void rope_kernel(const float* __restrict__ cosT,
                            const float* __restrict__ sinT)
{
    int idx = blockIdx.x * blockDim.x + threadIdx.x;   // over B*H*S*64
    int d  = idx & 63;
    int s  = (idx >> 6) & (S_ - 1);
    int bh = idx >> 17;
    size_t base = ((size_t)bh * S_ + s) * HD_;
    float c  = cosT[s*HD_ + d];
    float sn = sinT[s*HD_ + d];

    float q1 = g_q[base + d], q2 = g_q[base + d + 64];
    g_q[base + d]      = q1*c - q2*sn;
    g_q[base + d + 64] = q2*c + q1*sn;

    float k1 = g_k[base + d], k2 = g_k[base + d + 64];
    g_k[base + d]      = k1*c - k2*sn;
    g_k[base + d + 64] = k2*c + k1*sn;
}

// =====================================================================
// Flash attention (fp32 FFMA), causal. 64x64 blocks, HD=128.
// =====================================================================
#define QSTR 132
#define PSTR 68
#define ATT_SMEM ((3*64*QSTR + 64*PSTR) * 4)

__global__ __launch_bounds__(256, 1) void attn_kernel()
{
    extern __shared__ float sm[];
    float* Qs = sm;
    float* Ks = sm + 64*QSTR;
    float* Vs = sm + 2*64*QSTR;
    float* Ps = sm + 3*64*QSTR;

    const int tid = threadIdx.x;
    const int tx  = tid & 15;
    const int ty  = tid >> 4;
    const int qb  = (int)(gridDim.x - 1 - blockIdx.x);
    const int bh  = blockIdx.y;
    const int q0  = qb * 64;

    const float* qp = g_q + (size_t)bh * S_ * HD_;
    const float* kp = g_k + (size_t)bh * S_ * HD_;
    const float* vp = g_v + (size_t)bh * S_ * HD_;

#pragma unroll
    for (int i = 0; i < 8; i++) {
        int pos = i*256 + tid;
        int row = pos >> 5;
        int kc  = (pos & 31) << 2;
        *(float4*)&Qs[row*QSTR + kc] =
            *(const float4*)&qp[(size_t)(q0 + row) * HD_ + kc];
    }

    float m_i[4], l_i[4], o_[4][8];
#pragma unroll
    for (int i = 0; i < 4; i++) {
        m_i[i] = -INFINITY; l_i[i] = 0.f;
#pragma unroll
        for (int c = 0; c < 8; c++) o_[i][c] = 0.f;
    }

    for (int kb = 0; kb <= q0; kb += 64) {
        __syncthreads();
#pragma unroll
        for (int i = 0; i < 8; i++) {
            int pos = i*256 + tid;
            int row = pos >> 5;
            int kc  = (pos & 31) << 2;
            *(float4*)&Ks[row*QSTR + kc] =
                *(const float4*)&kp[(size_t)(kb + row) * HD_ + kc];
            *(float4*)&Vs[row*QSTR + kc] =
                *(const float4*)&vp[(size_t)(kb + row) * HD_ + kc];
        }
        __syncthreads();

        float rs[4][4];
#pragma unroll
        for (int i = 0; i < 4; i++)
#pragma unroll
            for (int j = 0; j < 4; j++) rs[i][j] = 0.f;

#pragma unroll 8
        for (int kk = 0; kk < HD_; kk += 4) {
            float4 q4[4], k4[4];
#pragma unroll
            for (int i = 0; i < 4; i++)
                q4[i] = *(float4*)&Qs[(ty + 16*i)*QSTR + kk];
#pragma unroll
            for (int j = 0; j < 4; j++)
                k4[j] = *(float4*)&Ks[(tx + 16*j)*QSTR + kk];
#pragma unroll
            for (int i = 0; i < 4; i++)
#pragma unroll
                for (int j = 0; j < 4; j++) {
                    rs[i][j] += q4[i].x*k4[j].x;
                    rs[i][j] += q4[i].y*k4[j].y;
                    rs[i][j] += q4[i].z*k4[j].z;
                    rs[i][j] += q4[i].w*k4[j].w;
                }
        }

        const bool diag = (kb == q0);
#pragma unroll
        for (int i = 0; i < 4; i++) {
            int r = ty + 16*i;
            float mx = -INFINITY;
#pragma unroll
            for (int j = 0; j < 4; j++) {
                float v = rs[i][j] * SCALE_;
                if (diag && (tx + 16*j > r)) v = -INFINITY;
                rs[i][j] = v;
                mx = fmaxf(mx, v);
            }
            mx = fmaxf(mx, __shfl_xor_sync(0xffffffffu, mx, 1));
            mx = fmaxf(mx, __shfl_xor_sync(0xffffffffu, mx, 2));
            mx = fmaxf(mx, __shfl_xor_sync(0xffffffffu, mx, 4));
            mx = fmaxf(mx, __shfl_xor_sync(0xffffffffu, mx, 8));

            float mnew = fmaxf(m_i[i], mx);
            float corr = __expf(m_i[i] - mnew);
            m_i[i] = mnew;
            l_i[i] *= corr;
#pragma unroll
            for (int c = 0; c < 8; c++) o_[i][c] *= corr;

            float ps = 0.f;
#pragma unroll
            for (int j = 0; j < 4; j++) {
                float p = __expf(rs[i][j] - mnew);
                Ps[r*PSTR + tx + 16*j] = p;
                ps += p;
            }
            l_i[i] += ps;
        }
        __syncthreads();

#pragma unroll 4
        for (int j = 0; j < 64; j++) {
            float4 v0 = *(float4*)&Vs[j*QSTR + tx*4];
            float4 v1 = *(float4*)&Vs[j*QSTR + 64 + tx*4];
#pragma unroll
            for (int i = 0; i < 4; i++) {
                float p = Ps[(ty + 16*i)*PSTR + j];
                o_[i][0] += p*v0.x; o_[i][1] += p*v0.y;
                o_[i][2] += p*v0.z; o_[i][3] += p*v0.w;
                o_[i][4] += p*v1.x; o_[i][5] += p*v1.y;
                o_[i][6] += p*v1.z; o_[i][7] += p*v1.w;
            }
        }
    }

    const int b = bh >> 4, h = bh & 15;
#pragma unroll
    for (int i = 0; i < 4; i++) {
        float lt = l_i[i];
        lt += __shfl_xor_sync(0xffffffffu, lt, 1);
        lt += __shfl_xor_sync(0xffffffffu, lt, 2);
        lt += __shfl_xor_sync(0xffffffffu, lt, 4);
        lt += __shfl_xor_sync(0xffffffffu, lt, 8);
        float inv = 1.f / lt;
        int s = q0 + ty + 16*i;
        float* op = g_ao + ((size_t)(b*S_ + s)) * D_ + h*HD_;
        float4 w0 = make_float4(o_[i][0]*inv, o_[i][1]*inv, o_[i][2]*inv, o_[i][3]*inv);
        float4 w1 = make_float4(o_[i][4]*inv, o_[i][5]*inv, o_[i][6]*inv, o_[i][7]*inv);
        *(float4*)&op[tx*4]      = w0;
        *(float4*)&op[64 + tx*4] = w1;
    }
}

// =====================================================================
extern "C" void kernel_launch(void* const* d_in, const int* in_sizes, int n_in,
                              void* d_out, int out_size)
{
    (void)in_sizes; (void)n_in; (void)out_size;
    const float* x    = (const float*)d_in[0];
    // d_in[1] = mask: exactly causal, implemented analytically
    const float* cosT = (const float*)d_in[2];
    const float* sinT = (const float*)d_in[3];
    const float* Wq   = (const float*)d_in[4];
    const float* Wk   = (const float*)d_in[5];
    const float* Wv   = (const float*)d_in[6];
    const float* Wo   = (const float*)d_in[7];
    float* out = (float*)d_out;

    cudaFuncSetAttribute(gemm_mma,
        cudaFuncAttributeMaxDynamicSharedMemorySize, GSMEM);
    cudaFuncSetAttribute(attn_kernel,
        cudaFuncAttributeMaxDynamicSharedMemorySize, ATT_SMEM);

    // 1) fused QKV projection (mma.sync bf16-split) -> [B,H,S,HD]
    dim3 gqkv(D_/128, M_/128, 3);
    gemm_mma<<<gqkv, 512, GSMEM>>>(x, Wq, Wk, Wv, nullptr, 1);

    // 2) RoPE in place on q,k
    rope_kernel<<<(B_*H_*S_*64)/256, 256>>>(cosT, sinT);

    // 3) causal flash attention -> g_ao [B,S,D]
    dim3 gatt(S_/64, B_*H_);
    attn_kernel<<<gatt, 256, ATT_SMEM>>>();

    // 4) output projection
    dim3 go(D_/128, M_/128, 1);
    gemm_mma<<<go, 512, GSMEM>>>(nullptr, Wo, nullptr, nullptr, out, 0);
}

// round 4
// speedup vs baseline: 2.5115x; 1.4306x over previous
#include <cuda_runtime.h>
#include <cuda_bf16.h>
#include <math.h>

#define B_  2
#define S_  2048
#define D_  2048
#define H_  16
#define HD_ 128
#define M_  (B_*S_)          // 4096

#define SCALE_ 0.08838834764831845f   // 1/sqrt(128)

// -------- scratch (allocation-free rule: __device__ globals) --------
static __device__ float g_q [B_*H_*S_*HD_];
static __device__ float g_k [B_*H_*S_*HD_];
static __device__ float g_v [B_*H_*S_*HD_];
static __device__ float g_ao[B_*S_*D_];

// ===================== helpers =========================
__device__ __forceinline__ unsigned smem_u32(const void* p) {
    unsigned a;
    asm("{ .reg .u64 t; cvta.to.shared.u64 t, %1; cvt.u32.u64 %0, t; }"
        : "=r"(a) : "l"(p));
    return a;
}

#define LDSM4(r0,r1,r2,r3,a) \
    asm volatile("ldmatrix.sync.aligned.m8n8.x4.shared.b16 {%0,%1,%2,%3}, [%4];" \
        : "=r"(r0),"=r"(r1),"=r"(r2),"=r"(r3) : "r"(a))

#define MMA16816(d, a0,a1,a2,a3, b0,b1) \
    asm volatile("mma.sync.aligned.m16n8k16.row.col.f32.bf16.bf16.f32 " \
        "{%0,%1,%2,%3}, {%4,%5,%6,%7}, {%8,%9}, {%0,%1,%2,%3};" \
        : "+f"((d)[0]),"+f"((d)[1]),"+f"((d)[2]),"+f"((d)[3]) \
        : "r"(a0),"r"(a1),"r"(a2),"r"(a3),"r"(b0),"r"(b1))

#define MMAT32(d, a0,a1,a2,a3, b0,b1) \
    asm volatile("mma.sync.aligned.m16n8k8.row.col.f32.tf32.tf32.f32 " \
        "{%0,%1,%2,%3}, {%4,%5,%6,%7}, {%8,%9}, {%0,%1,%2,%3};" \
        : "+f"((d)[0]),"+f"((d)[1]),"+f"((d)[2]),"+f"((d)[3]) \
        : "r"(a0),"r"(a1),"r"(a2),"r"(a3),"r"(b0),"r"(b1))

__device__ __forceinline__ float to_tf32(float x) {
    unsigned r;
    asm("cvt.rna.tf32.f32 %0, %1;" : "=r"(r) : "f"(x));
    return __uint_as_float(r);
}
__device__ __forceinline__ unsigned to_tf32u(float x) {
    unsigned r;
    asm("cvt.rna.tf32.f32 %0, %1;" : "=r"(r) : "f"(x));
    return r;
}

// fp32 -> (hi, lo) bf16 split, packed 2x2
__device__ __forceinline__ void cvt_split(float4 v, uint2& hi, uint2& lo) {
    unsigned h01, h23;
    asm("cvt.rn.bf16x2.f32 %0, %1, %2;" : "=r"(h01) : "f"(v.y), "f"(v.x));
    asm("cvt.rn.bf16x2.f32 %0, %1, %2;" : "=r"(h23) : "f"(v.w), "f"(v.z));
    float hx = __uint_as_float(h01 << 16), hy = __uint_as_float(h01 & 0xFFFF0000u);
    float hz = __uint_as_float(h23 << 16), hw = __uint_as_float(h23 & 0xFFFF0000u);
    unsigned l01, l23;
    asm("cvt.rn.bf16x2.f32 %0, %1, %2;" : "=r"(l01) : "f"(v.y - hy), "f"(v.x - hx));
    asm("cvt.rn.bf16x2.f32 %0, %1, %2;" : "=r"(l23) : "f"(v.w - hw), "f"(v.z - hz));
    hi.x = h01; hi.y = h23; lo.x = l01; lo.y = l23;
}

// =====================================================================
// Tensor-core (mma.sync bf16) NT GEMM with 2-way split (hh + lh + hl).
// Unchanged from round 3 (passed @ 48.9% tensor util).
// =====================================================================
#define GBK 32
#define GNCH (D_/GBK)      // 64
#define RS 40
#define AH_OFF 0
#define AL_OFF 10240
#define BH_OFF 20480
#define BL_OFF 30720
#define STG_BYTES 40960
#define GSMEM (2*STG_BYTES)   // 81920

__global__ __launch_bounds__(512, 1) void gemm_mma(
    const float* __restrict__ A,
    const float* __restrict__ W0, const float* __restrict__ W1,
    const float* __restrict__ W2,
    float* __restrict__ Cout, int scatter)
{
    extern __shared__ char sm_[];
    const unsigned sbase = smem_u32(sm_);

    const int tid = threadIdx.x;
    const int wid = tid >> 5, lid = tid & 31;
    const int m0 = blockIdx.y * 128;
    const int n0 = blockIdx.x * 128;

    const float* W = W0;
    const float* Ap = A;
    float* outq = nullptr;
    if (scatter) {
        if (blockIdx.z == 1)      W = W1;
        else if (blockIdx.z == 2) W = W2;
        outq = (blockIdx.z == 0) ? g_q : (blockIdx.z == 1) ? g_k : g_v;
    } else {
        Ap = g_ao;
    }

    const int wm = wid >> 2, wn = wid & 3;

    const int arow = wm*32 + (lid & 7) + ((lid & 8) ? 8 : 0);
    const int acol = (lid & 16) ? 8 : 0;
    const unsigned aoff0 = (unsigned)(arow * RS + acol) * 2u;
    const int brow = wn*32 + (lid & 7) + ((lid & 16) ? 8 : 0);
    const int bcol = (lid & 8) ? 8 : 0;
    const unsigned boff0 = (unsigned)(brow * RS + bcol) * 2u;

    const int r0i = tid >> 3, q0i = tid & 7;
    const int r1i = (tid + 512) >> 3, q1i = tid & 7;

    float acc[2][4][4];
#pragma unroll
    for (int mt = 0; mt < 2; mt++)
#pragma unroll
        for (int nt = 0; nt < 4; nt++)
#pragma unroll
            for (int e = 0; e < 4; e++) acc[mt][nt][e] = 0.f;

    float4 pa[2], pb[2];

    pa[0] = *(const float4*)(Ap + (size_t)(m0 + r0i) * D_ + q0i*4);
    pa[1] = *(const float4*)(Ap + (size_t)(m0 + r1i) * D_ + q1i*4);
    pb[0] = *(const float4*)(W  + (size_t)(n0 + r0i) * D_ + q0i*4);
    pb[1] = *(const float4*)(W  + (size_t)(n0 + r1i) * D_ + q1i*4);
    {
        char* st0 = sm_;
        uint2 hi, lo;
        cvt_split(pa[0], hi, lo);
        *(uint2*)(st0 + AH_OFF + r0i*80 + q0i*8) = hi;
        *(uint2*)(st0 + AL_OFF + r0i*80 + q0i*8) = lo;
        cvt_split(pa[1], hi, lo);
        *(uint2*)(st0 + AH_OFF + r1i*80 + q1i*8) = hi;
        *(uint2*)(st0 + AL_OFF + r1i*80 + q1i*8) = lo;
        cvt_split(pb[0], hi, lo);
        *(uint2*)(st0 + BH_OFF + r0i*80 + q0i*8) = hi;
        *(uint2*)(st0 + BL_OFF + r0i*80 + q0i*8) = lo;
        cvt_split(pb[1], hi, lo);
        *(uint2*)(st0 + BH_OFF + r1i*80 + q1i*8) = hi;
        *(uint2*)(st0 + BL_OFF + r1i*80 + q1i*8) = lo;
    }
    __syncthreads();

#pragma unroll 1
    for (int c = 0; c < GNCH; c++) {
        if (c + 1 < GNCH) {
            int k0 = (c + 1) * GBK;
            pa[0] = *(const float4*)(Ap + (size_t)(m0 + r0i) * D_ + k0 + q0i*4);
            pa[1] = *(const float4*)(Ap + (size_t)(m0 + r1i) * D_ + k0 + q1i*4);
            pb[0] = *(const float4*)(W  + (size_t)(n0 + r0i) * D_ + k0 + q0i*4);
            pb[1] = *(const float4*)(W  + (size_t)(n0 + r1i) * D_ + k0 + q1i*4);
        }

        const unsigned sA = sbase + (unsigned)(c & 1) * STG_BYTES;
#pragma unroll
        for (int ks = 0; ks < 2; ks++) {
            const unsigned kso = (unsigned)(ks * 16 * 2);
            unsigned ah[2][4], al[2][4], bb[2][4];
#pragma unroll
            for (int mt = 0; mt < 2; mt++)
                LDSM4(ah[mt][0],ah[mt][1],ah[mt][2],ah[mt][3],
                      sA + AH_OFF + aoff0 + (unsigned)(mt*16*RS*2) + kso);
#pragma unroll
            for (int mt = 0; mt < 2; mt++)
                LDSM4(al[mt][0],al[mt][1],al[mt][2],al[mt][3],
                      sA + AL_OFF + aoff0 + (unsigned)(mt*16*RS*2) + kso);
#pragma unroll
            for (int p = 0; p < 2; p++)
                LDSM4(bb[p][0],bb[p][1],bb[p][2],bb[p][3],
                      sA + BH_OFF + boff0 + (unsigned)(p*16*RS*2) + kso);
#pragma unroll
            for (int mt = 0; mt < 2; mt++)
#pragma unroll
                for (int p = 0; p < 2; p++) {
                    MMA16816(acc[mt][2*p],   ah[mt][0],ah[mt][1],ah[mt][2],ah[mt][3], bb[p][0],bb[p][1]);
                    MMA16816(acc[mt][2*p+1], ah[mt][0],ah[mt][1],ah[mt][2],ah[mt][3], bb[p][2],bb[p][3]);
                }
#pragma unroll
            for (int mt = 0; mt < 2; mt++)
#pragma unroll
                for (int p = 0; p < 2; p++) {
                    MMA16816(acc[mt][2*p],   al[mt][0],al[mt][1],al[mt][2],al[mt][3], bb[p][0],bb[p][1]);
                    MMA16816(acc[mt][2*p+1], al[mt][0],al[mt][1],al[mt][2],al[mt][3], bb[p][2],bb[p][3]);
                }
#pragma unroll
            for (int p = 0; p < 2; p++)
                LDSM4(bb[p][0],bb[p][1],bb[p][2],bb[p][3],
                      sA + BL_OFF + boff0 + (unsigned)(p*16*RS*2) + kso);
#pragma unroll
            for (int mt = 0; mt < 2; mt++)
#pragma unroll
                for (int p = 0; p < 2; p++) {
                    MMA16816(acc[mt][2*p],   ah[mt][0],ah[mt][1],ah[mt][2],ah[mt][3], bb[p][0],bb[p][1]);
                    MMA16816(acc[mt][2*p+1], ah[mt][0],ah[mt][1],ah[mt][2],ah[mt][3], bb[p][2],bb[p][3]);
                }
        }

        if (c + 1 < GNCH) {
            char* st = sm_ + ((c + 1) & 1) * STG_BYTES;
            uint2 hi, lo;
            cvt_split(pa[0], hi, lo);
            *(uint2*)(st + AH_OFF + r0i*80 + q0i*8) = hi;
            *(uint2*)(st + AL_OFF + r0i*80 + q0i*8) = lo;
            cvt_split(pa[1], hi, lo);
            *(uint2*)(st + AH_OFF + r1i*80 + q1i*8) = hi;
            *(uint2*)(st + AL_OFF + r1i*80 + q1i*8) = lo;
            cvt_split(pb[0], hi, lo);
            *(uint2*)(st + BH_OFF + r0i*80 + q0i*8) = hi;
            *(uint2*)(st + BL_OFF + r0i*80 + q0i*8) = lo;
            cvt_split(pb[1], hi, lo);
            *(uint2*)(st + BH_OFF + r1i*80 + q1i*8) = hi;
            *(uint2*)(st + BL_OFF + r1i*80 + q1i*8) = lo;
        }
        __syncthreads();
    }

#pragma unroll
    for (int mt = 0; mt < 2; mt++)
#pragma unroll
    for (int nt = 0; nt < 4; nt++) {
        int r  = m0 + wm*32 + mt*16 + (lid >> 2);
        int cc = n0 + wn*32 + nt*8 + (lid & 3)*2;
        if (!scatter) {
            *(float2*)(Cout + (size_t)r * D_ + cc) =
                make_float2(acc[mt][nt][0], acc[mt][nt][1]);
            *(float2*)(Cout + (size_t)(r + 8) * D_ + cc) =
                make_float2(acc[mt][nt][2], acc[mt][nt][3]);
        } else {
            int h = cc >> 7, cd = cc & 127;
            int b1 = r >> 11, s1 = r & (S_ - 1);
            *(float2*)(outq + ((size_t)(b1*H_ + h) * S_ + s1) * HD_ + cd) =
                make_float2(acc[mt][nt][0], acc[mt][nt][1]);
            int r2 = r + 8;
            int b2 = r2 >> 11, s2 = r2 & (S_ - 1);
            *(float2*)(outq + ((size_t)(b2*H_ + h) * S_ + s2) * HD_ + cd) =
                make_float2(acc[mt][nt][2], acc[mt][nt][3]);
        }
    }
}

// =====================================================================
// RoPE in-place on g_q and g_k.
// =====================================================================
__global__ void rope_kernel(const float* __restrict__ cosT,
                            const float* __restrict__ sinT)
{
    int idx = blockIdx.x * blockDim.x + threadIdx.x;
    int d  = idx & 63;
    int s  = (idx >> 6) & (S_ - 1);
    int bh = idx >> 17;
    size_t base = ((size_t)bh * S_ + s) * HD_;
    float c  = cosT[s*HD_ + d];
    float sn = sinT[s*HD_ + d];

    float q1 = g_q[base + d], q2 = g_q[base + d + 64];
    g_q[base + d]      = q1*c - q2*sn;
    g_q[base + d + 64] = q2*c + q1*sn;

    float k1 = g_k[base + d], k2 = g_k[base + d + 64];
    g_k[base + d]      = k1*c - k2*sn;
    g_k[base + d + 64] = k2*c + k1*sn;
}

// =====================================================================
// Flash attention on tf32 tensor cores. BQ=128, BK=64, 8 warps.
// Each warp owns 16 q-rows x all 64 keys (no cross-warp softmax).
// P kept in registers (quad shuffle -> A fragments). V staged transposed.
// =====================================================================
#define QS_STR 132
#define VT_STR 68
#define KS_OFF (128*132)                 // floats
#define VT_OFF (KS_OFF + 64*132)         // 25344
#define ATT2_SMEM ((VT_OFF + 128*VT_STR) * 4)   // 136192 bytes

__global__ __launch_bounds__(256, 1) void attn_tc()
{
    extern __shared__ float sm[];
    float* Qs = sm;
    float* Ks = sm + KS_OFF;
    float* VT = sm + VT_OFF;

    const int tid = threadIdx.x;
    const int wid = tid >> 5, lid = tid & 31;
    const int qb  = 15 - (int)blockIdx.x;     // big q-blocks first
    const int bh  = blockIdx.y;
    const int q0  = qb * 128;

    const float* qp = g_q + (size_t)bh * S_ * HD_;
    const float* kp = g_k + (size_t)bh * S_ * HD_;
    const float* vp = g_v + (size_t)bh * S_ * HD_;

    // ---- load Q tile (tf32-rounded) ----
#pragma unroll
    for (int i = 0; i < 16; i++) {
        int pos = i*256 + tid;            // 4096 float4s
        int row = pos >> 5;
        int c4  = (pos & 31) << 2;
        float4 v = *(const float4*)&qp[(size_t)(q0 + row) * HD_ + c4];
        v.x = to_tf32(v.x); v.y = to_tf32(v.y);
        v.z = to_tf32(v.z); v.w = to_tf32(v.w);
        *(float4*)&Qs[row*QS_STR + c4] = v;
    }

    const int a_ = lid >> 2, q_ = lid & 3;
    const int r0g = q0 + wid*16 + a_;         // this thread's row (and +8)

    // ldmatrix lane bases
    const unsigned aq_base = smem_u32(Qs) +
        (unsigned)(((wid*16 + (lid & 7) + ((lid & 8) ? 8 : 0)) * QS_STR
                    + ((lid & 16) ? 4 : 0)) * 4);
    const unsigned ks_lane = smem_u32(Ks) +
        (unsigned)((((lid & 7) + ((lid & 16) ? 8 : 0)) * QS_STR
                    + ((lid & 8) ? 4 : 0)) * 4);
    const unsigned vt_lane = smem_u32(VT) +
        (unsigned)((((lid & 7) + ((lid & 16) ? 8 : 0)) * VT_STR
                    + ((lid & 8) ? 4 : 0)) * 4);

    float m0 = -INFINITY, m1 = -INFINITY, l0 = 0.f, l1 = 0.f;
    float o[16][4];
#pragma unroll
    for (int f = 0; f < 16; f++)
#pragma unroll
        for (int e = 0; e < 4; e++) o[f][e] = 0.f;

    const int src  = (lid & 0x1C) | (q_ >> 1);
    const int src2 = src + 2;
    const int par  = q_ & 1;

    const int nt = 2*qb + 2;
#pragma unroll 1
    for (int t = 0; t < nt; t++) {
        const int kb = t * 64;
        __syncthreads();
        // ---- stage K (row-major) and V (transposed) as tf32 ----
#pragma unroll
        for (int i = 0; i < 8; i++) {
            int pos = i*256 + tid;        // 2048 float4s
            int row = pos >> 5;
            int c4  = (pos & 31) << 2;
            float4 v = *(const float4*)&kp[(size_t)(kb + row) * HD_ + c4];
            v.x = to_tf32(v.x); v.y = to_tf32(v.y);
            v.z = to_tf32(v.z); v.w = to_tf32(v.w);
            *(float4*)&Ks[row*QS_STR + c4] = v;
        }
#pragma unroll
        for (int i = 0; i < 32; i++) {
            int pos = i*256 + tid;        // 8192 scalars
            int key = pos >> 7, hd = pos & 127;
            VT[hd*VT_STR + key] = to_tf32(vp[(size_t)(kb + key) * HD_ + hd]);
        }
        __syncthreads();

        // ---- QK^T: scores 16 x 64 per warp ----
        float sc[8][4];
#pragma unroll
        for (int f = 0; f < 8; f++)
#pragma unroll
            for (int e = 0; e < 4; e++) sc[f][e] = 0.f;

#pragma unroll
        for (int kc = 0; kc < 16; kc++) {
            unsigned a0, a1, a2, a3;
            LDSM4(a0, a1, a2, a3, aq_base + (unsigned)(kc*32));
#pragma unroll
            for (int p = 0; p < 4; p++) {
                unsigned b0, b1, b2, b3;
                LDSM4(b0, b1, b2, b3,
                      ks_lane + (unsigned)((p*16*QS_STR + kc*8) * 4));
                MMAT32(sc[2*p],   a0, a1, a2, a3, b0, b1);
                MMAT32(sc[2*p+1], a0, a1, a2, a3, b2, b3);
            }
        }

        // ---- online softmax (rows r0g, r0g+8) ----
        const bool maskt = (kb + 63 > q0);
        float mx0 = -INFINITY, mx1 = -INFINITY;
#pragma unroll
        for (int f = 0; f < 8; f++) {
            int cg = kb + f*8 + q_*2;
            float v0 = sc[f][0]*SCALE_, v1 = sc[f][1]*SCALE_;
            float v2 = sc[f][2]*SCALE_, v3 = sc[f][3]*SCALE_;
            if (maskt) {
                if (cg     > r0g)     v0 = -INFINITY;
                if (cg + 1 > r0g)     v1 = -INFINITY;
                if (cg     > r0g + 8) v2 = -INFINITY;
                if (cg + 1 > r0g + 8) v3 = -INFINITY;
            }
            sc[f][0] = v0; sc[f][1] = v1; sc[f][2] = v2; sc[f][3] = v3;
            mx0 = fmaxf(mx0, fmaxf(v0, v1));
            mx1 = fmaxf(mx1, fmaxf(v2, v3));
        }
        mx0 = fmaxf(mx0, __shfl_xor_sync(0xffffffffu, mx0, 1));
        mx0 = fmaxf(mx0, __shfl_xor_sync(0xffffffffu, mx0, 2));
        mx1 = fmaxf(mx1, __shfl_xor_sync(0xffffffffu, mx1, 1));
        mx1 = fmaxf(mx1, __shfl_xor_sync(0xffffffffu, mx1, 2));

        float mn0 = fmaxf(m0, mx0), mn1 = fmaxf(m1, mx1);
        float cr0 = __expf(m0 - mn0), cr1 = __expf(m1 - mn1);
        m0 = mn0; m1 = mn1;
#pragma unroll
        for (int f = 0; f < 16; f++) {
            o[f][0] *= cr0; o[f][1] *= cr0;
            o[f][2] *= cr1; o[f][3] *= cr1;
        }
        float s0 = 0.f, s1 = 0.f;
#pragma unroll
        for (int f = 0; f < 8; f++) {
            float p0 = __expf(sc[f][0] - mn0);
            float p1 = __expf(sc[f][1] - mn0);
            float p2 = __expf(sc[f][2] - mn1);
            float p3 = __expf(sc[f][3] - mn1);
            sc[f][0] = p0; sc[f][1] = p1; sc[f][2] = p2; sc[f][3] = p3;
            s0 += p0 + p1; s1 += p2 + p3;
        }
        l0 = l0*cr0 + s0; l1 = l1*cr1 + s1;

        // ---- P @ V: o[16x128] += P[16x64] V[64x128] ----
#pragma unroll
        for (int kc8 = 0; kc8 < 8; kc8++) {
            float e0a = __shfl_sync(0xffffffffu, sc[kc8][0], src);
            float e0b = __shfl_sync(0xffffffffu, sc[kc8][1], src);
            float e1a = __shfl_sync(0xffffffffu, sc[kc8][2], src);
            float e1b = __shfl_sync(0xffffffffu, sc[kc8][3], src);
            float e2a = __shfl_sync(0xffffffffu, sc[kc8][0], src2);
            float e2b = __shfl_sync(0xffffffffu, sc[kc8][1], src2);
            float e3a = __shfl_sync(0xffffffffu, sc[kc8][2], src2);
            float e3b = __shfl_sync(0xffffffffu, sc[kc8][3], src2);
            unsigned pa0 = to_tf32u(par ? e0b : e0a);
            unsigned pa1 = to_tf32u(par ? e1b : e1a);
            unsigned pa2 = to_tf32u(par ? e2b : e2a);
            unsigned pa3 = to_tf32u(par ? e3b : e3a);
#pragma unroll
            for (int g = 0; g < 8; g++) {
                unsigned v0, v1, v2, v3;
                LDSM4(v0, v1, v2, v3,
                      vt_lane + (unsigned)((g*16*VT_STR + kc8*8) * 4));
                MMAT32(o[2*g],   pa0, pa1, pa2, pa3, v0, v1);
                MMAT32(o[2*g+1], pa0, pa1, pa2, pa3, v2, v3);
            }
        }
    }

    // ---- normalize & write [B,S,H*HD] ----
    l0 += __shfl_xor_sync(0xffffffffu, l0, 1);
    l0 += __shfl_xor_sync(0xffffffffu, l0, 2);
    l1 += __shfl_xor_sync(0xffffffffu, l1, 1);
    l1 += __shfl_xor_sync(0xffffffffu, l1, 2);
    float inv0 = 1.f / l0, inv1 = 1.f / l1;

    const int b = bh >> 4, h = bh & 15;
    const int row0 = q0 + wid*16 + a_;
    float* op0 = g_ao + ((size_t)(b*S_ + row0))     * D_ + h*HD_;
    float* op1 = g_ao + ((size_t)(b*S_ + row0 + 8)) * D_ + h*HD_;
#pragma unroll
    for (int f = 0; f < 16; f++) {
        int c = f*8 + q_*2;
        *(float2*)&op0[c] = make_float2(o[f][0]*inv0, o[f][1]*inv0);
        *(float2*)&op1[c] = make_float2(o[f][2]*inv1, o[f][3]*inv1);
    }
}

// =====================================================================
extern "C" void kernel_launch(void* const* d_in, const int* in_sizes, int n_in,
                              void* d_out, int out_size)
{
    (void)in_sizes; (void)n_in; (void)out_size;
    const float* x    = (const float*)d_in[0];
    // d_in[1] = mask: exactly causal, implemented analytically
    const float* cosT = (const float*)d_in[2];
    const float* sinT = (const float*)d_in[3];
    const float* Wq   = (const float*)d_in[4];
    const float* Wk   = (const float*)d_in[5];
    const float* Wv   = (const float*)d_in[6];
    const float* Wo   = (const float*)d_in[7];
    float* out = (float*)d_out;

    cudaFuncSetAttribute(gemm_mma,
        cudaFuncAttributeMaxDynamicSharedMemorySize, GSMEM);
    cudaFuncSetAttribute(attn_tc,
        cudaFuncAttributeMaxDynamicSharedMemorySize, ATT2_SMEM);

    // 1) fused QKV projection (mma.sync bf16-split) -> [B,H,S,HD]
    dim3 gqkv(D_/128, M_/128, 3);
    gemm_mma<<<gqkv, 512, GSMEM>>>(x, Wq, Wk, Wv, nullptr, 1);

    // 2) RoPE in place on q,k
    rope_kernel<<<(B_*H_*S_*64)/256, 256>>>(cosT, sinT);

    // 3) causal flash attention (tf32 tensor cores) -> g_ao [B,S,D]
    dim3 gatt(S_/128, B_*H_);
    attn_tc<<<gatt, 256, ATT2_SMEM>>>();

    // 4) output projection
    dim3 go(D_/128, M_/128, 1);
    gemm_mma<<<go, 512, GSMEM>>>(nullptr, Wo, nullptr, nullptr, out, 0);
}

// round 5
// speedup vs baseline: 3.0551x; 1.2164x over previous
#include <cuda_runtime.h>
#include <cuda_bf16.h>
#include <math.h>

#define B_  2
#define S_  2048
#define D_  2048
#define H_  16
#define HD_ 128
#define M_  (B_*S_)          // 4096

#define SCALE_ 0.08838834764831845f   // 1/sqrt(128)

// -------- scratch (allocation-free rule: __device__ globals) --------
static __device__ float g_q [B_*H_*S_*HD_];
static __device__ float g_k [B_*H_*S_*HD_];
static __device__ float g_v [B_*H_*S_*HD_];
static __device__ float g_ao[B_*S_*D_];

// ===================== helpers =========================
__device__ __forceinline__ unsigned smem_u32(const void* p) {
    unsigned a;
    asm("{ .reg .u64 t; cvta.to.shared.u64 t, %1; cvt.u32.u64 %0, t; }"
        : "=r"(a) : "l"(p));
    return a;
}

#define LDSM4(r0,r1,r2,r3,a) \
    asm volatile("ldmatrix.sync.aligned.m8n8.x4.shared.b16 {%0,%1,%2,%3}, [%4];" \
        : "=r"(r0),"=r"(r1),"=r"(r2),"=r"(r3) : "r"(a))

#define MMAT32(d, a0,a1,a2,a3, b0,b1) \
    asm volatile("mma.sync.aligned.m16n8k8.row.col.f32.tf32.tf32.f32 " \
        "{%0,%1,%2,%3}, {%4,%5,%6,%7}, {%8,%9}, {%0,%1,%2,%3};" \
        : "+f"((d)[0]),"+f"((d)[1]),"+f"((d)[2]),"+f"((d)[3]) \
        : "r"(a0),"r"(a1),"r"(a2),"r"(a3),"r"(b0),"r"(b1))

__device__ __forceinline__ float to_tf32(float x) {
    unsigned r;
    asm("cvt.rna.tf32.f32 %0, %1;" : "=r"(r) : "f"(x));
    return __uint_as_float(r);
}
__device__ __forceinline__ unsigned to_tf32u(float x) {
    unsigned r;
    asm("cvt.rna.tf32.f32 %0, %1;" : "=r"(r) : "f"(x));
    return r;
}
__device__ __forceinline__ float4 tf32_4(float4 v) {
    v.x = to_tf32(v.x); v.y = to_tf32(v.y);
    v.z = to_tf32(v.z); v.w = to_tf32(v.w);
    return v;
}

// =====================================================================
// tf32 NT GEMM: C[m,n] = sum_k A[m,k] * W[n,k].
// Tile 128x128, BK=64, 512 threads (4x4 warp grid, 32x32 warp tiles),
// double-buffered smem (stride 68 floats: conflict-free ldmatrix).
// scatter=1: z selects Wq/Wk/Wv, writes [B,H,S,HD] into g_q/g_k/g_v
// scatter=0: A := g_ao, W := W0 (Wo), row-major write to Cout
// =====================================================================
#define GBK 64
#define GNCH (D_/GBK)        // 32
#define GSTR 68              // floats per row
#define TILE_SZ (128*GSTR*4) // 34816 bytes (one 128x64 fp32 tile)
#define BUF_SZ  (2*TILE_SZ)  // A + B
#define GSMEM   (2*BUF_SZ)   // 139264

__global__ __launch_bounds__(512, 1) void gemm_tf32(
    const float* __restrict__ A,
    const float* __restrict__ W0, const float* __restrict__ W1,
    const float* __restrict__ W2,
    float* __restrict__ Cout, int scatter)
{
    extern __shared__ char sm_[];
    const unsigned sbase = smem_u32(sm_);

    const int tid = threadIdx.x;
    const int wid = tid >> 5, lid = tid & 31;
    const int m0 = blockIdx.y * 128;
    const int n0 = blockIdx.x * 128;

    const float* W = W0;
    const float* Ap = A;
    float* outq = nullptr;
    if (scatter) {
        if (blockIdx.z == 1)      W = W1;
        else if (blockIdx.z == 2) W = W2;
        outq = (blockIdx.z == 0) ? g_q : (blockIdx.z == 1) ? g_k : g_v;
    } else {
        Ap = g_ao;
    }

    const int wm = wid >> 2, wn = wid & 3;      // 4x4 warp grid, 32x32 tiles

    // ldmatrix lane bases (bytes within tile region)
    const unsigned aoff0 = (unsigned)(((wm*32 + (lid & 7) + ((lid & 8) ? 8 : 0)) * GSTR
                                       + ((lid & 16) ? 4 : 0)) * 4);
    const unsigned boff0 = (unsigned)(((wn*32 + (lid & 7) + ((lid & 16) ? 8 : 0)) * GSTR
                                       + ((lid & 8) ? 4 : 0)) * 4);

    // staging indices: 4 float4 per thread per operand tile
    // pos = tid + i*512 ; row = pos>>4 ; c4 = (pos&15)*4
    float acc[2][4][4];
#pragma unroll
    for (int mt = 0; mt < 2; mt++)
#pragma unroll
        for (int nt = 0; nt < 4; nt++)
#pragma unroll
            for (int e = 0; e < 4; e++) acc[mt][nt][e] = 0.f;

    float4 pa[4], pb[4];

    // ---- prologue: load + convert chunk 0 into buffer 0 ----
#pragma unroll
    for (int i = 0; i < 4; i++) {
        int pos = tid + i*512;
        int row = pos >> 4, c4 = (pos & 15) << 2;
        pa[i] = *(const float4*)(Ap + (size_t)(m0 + row) * D_ + c4);
        pb[i] = *(const float4*)(W  + (size_t)(n0 + row) * D_ + c4);
    }
    {
        char* st = sm_;
#pragma unroll
        for (int i = 0; i < 4; i++) {
            int pos = tid + i*512;
            int row = pos >> 4, c4 = (pos & 15) << 2;
            *(float4*)(st + (row*GSTR + c4)*4)           = tf32_4(pa[i]);
            *(float4*)(st + TILE_SZ + (row*GSTR + c4)*4) = tf32_4(pb[i]);
        }
    }
    __syncthreads();

#pragma unroll 1
    for (int c = 0; c < GNCH; c++) {
        // prefetch next chunk
        if (c + 1 < GNCH) {
            int k0 = (c + 1) * GBK;
#pragma unroll
            for (int i = 0; i < 4; i++) {
                int pos = tid + i*512;
                int row = pos >> 4, c4 = (pos & 15) << 2;
                pa[i] = *(const float4*)(Ap + (size_t)(m0 + row) * D_ + k0 + c4);
                pb[i] = *(const float4*)(W  + (size_t)(n0 + row) * D_ + k0 + c4);
            }
        }

        // ---- MMA over current buffer: 8 k8-steps ----
        const unsigned sA = sbase + (unsigned)(c & 1) * BUF_SZ;
        const unsigned sB = sA + TILE_SZ;
#pragma unroll
        for (int kc = 0; kc < 8; kc++) {
            const unsigned kso = (unsigned)(kc * 32);   // 8 floats
            unsigned a0[2], a1[2], a2[2], a3[2];
#pragma unroll
            for (int mt = 0; mt < 2; mt++)
                LDSM4(a0[mt], a1[mt], a2[mt], a3[mt],
                      sA + aoff0 + (unsigned)(mt*16*GSTR*4) + kso);
#pragma unroll
            for (int p = 0; p < 2; p++) {
                unsigned b0, b1, b2, b3;
                LDSM4(b0, b1, b2, b3,
                      sB + boff0 + (unsigned)(p*16*GSTR*4) + kso);
#pragma unroll
                for (int mt = 0; mt < 2; mt++) {
                    MMAT32(acc[mt][2*p],   a0[mt], a1[mt], a2[mt], a3[mt], b0, b1);
                    MMAT32(acc[mt][2*p+1], a0[mt], a1[mt], a2[mt], a3[mt], b2, b3);
                }
            }
        }

        // ---- store prefetched chunk into the other buffer ----
        if (c + 1 < GNCH) {
            char* st = sm_ + ((c + 1) & 1) * BUF_SZ;
#pragma unroll
            for (int i = 0; i < 4; i++) {
                int pos = tid + i*512;
                int row = pos >> 4, c4 = (pos & 15) << 2;
                *(float4*)(st + (row*GSTR + c4)*4)           = tf32_4(pa[i]);
                *(float4*)(st + TILE_SZ + (row*GSTR + c4)*4) = tf32_4(pb[i]);
            }
        }
        __syncthreads();
    }

    // ---- epilogue (c-fragment: rows lid>>2 / +8, cols (lid&3)*2) ----
#pragma unroll
    for (int mt = 0; mt < 2; mt++)
#pragma unroll
    for (int nt = 0; nt < 4; nt++) {
        int r  = m0 + wm*32 + mt*16 + (lid >> 2);
        int cc = n0 + wn*32 + nt*8 + (lid & 3)*2;
        if (!scatter) {
            *(float2*)(Cout + (size_t)r * D_ + cc) =
                make_float2(acc[mt][nt][0], acc[mt][nt][1]);
            *(float2*)(Cout + (size_t)(r + 8) * D_ + cc) =
                make_float2(acc[mt][nt][2], acc[mt][nt][3]);
        } else {
            int h = cc >> 7, cd = cc & 127;
            int b1 = r >> 11, s1 = r & (S_ - 1);
            *(float2*)(outq + ((size_t)(b1*H_ + h) * S_ + s1) * HD_ + cd) =
                make_float2(acc[mt][nt][0], acc[mt][nt][1]);
            int r2 = r + 8;
            int b2 = r2 >> 11, s2 = r2 & (S_ - 1);
            *(float2*)(outq + ((size_t)(b2*H_ + h) * S_ + s2) * HD_ + cd) =
                make_float2(acc[mt][nt][2], acc[mt][nt][3]);
        }
    }
}

// =====================================================================
// RoPE in-place on g_q and g_k.
// =====================================================================
__global__ void rope_kernel(const float* __restrict__ cosT,
                            const float* __restrict__ sinT)
{
    int idx = blockIdx.x * blockDim.x + threadIdx.x;
    int d  = idx & 63;
    int s  = (idx >> 6) & (S_ - 1);
    int bh = idx >> 17;
    size_t base = ((size_t)bh * S_ + s) * HD_;
    float c  = cosT[s*HD_ + d];
    float sn = sinT[s*HD_ + d];

    float q1 = g_q[base + d], q2 = g_q[base + d + 64];
    g_q[base + d]      = q1*c - q2*sn;
    g_q[base + d + 64] = q2*c + q1*sn;

    float k1 = g_k[base + d], k2 = g_k[base + d + 64];
    g_k[base + d]      = k1*c - k2*sn;
    g_k[base + d + 64] = k2*c + k1*sn;
}

// =====================================================================
// Flash attention on tf32 tensor cores. BQ=128, BK=64, 8 warps.
// (unchanged from round 4: 263us, works)
// =====================================================================
#define QS_STR 132
#define VT_STR 68
#define KS_OFF (128*132)
#define VT_OFF (KS_OFF + 64*132)
#define ATT2_SMEM ((VT_OFF + 128*VT_STR) * 4)   // 136192 bytes

__global__ __launch_bounds__(256, 1) void attn_tc()
{
    extern __shared__ float sm[];
    float* Qs = sm;
    float* Ks = sm + KS_OFF;
    float* VT = sm + VT_OFF;

    const int tid = threadIdx.x;
    const int wid = tid >> 5, lid = tid & 31;
    const int qb  = 15 - (int)blockIdx.x;
    const int bh  = blockIdx.y;
    const int q0  = qb * 128;

    const float* qp = g_q + (size_t)bh * S_ * HD_;
    const float* kp = g_k + (size_t)bh * S_ * HD_;
    const float* vp = g_v + (size_t)bh * S_ * HD_;

#pragma unroll
    for (int i = 0; i < 16; i++) {
        int pos = i*256 + tid;
        int row = pos >> 5;
        int c4  = (pos & 31) << 2;
        float4 v = *(const float4*)&qp[(size_t)(q0 + row) * HD_ + c4];
        *(float4*)&Qs[row*QS_STR + c4] = tf32_4(v);
    }

    const int a_ = lid >> 2, q_ = lid & 3;
    const int r0g = q0 + wid*16 + a_;

    const unsigned aq_base = smem_u32(Qs) +
        (unsigned)(((wid*16 + (lid & 7) + ((lid & 8) ? 8 : 0)) * QS_STR
                    + ((lid & 16) ? 4 : 0)) * 4);
    const unsigned ks_lane = smem_u32(Ks) +
        (unsigned)((((lid & 7) + ((lid & 16) ? 8 : 0)) * QS_STR
                    + ((lid & 8) ? 4 : 0)) * 4);
    const unsigned vt_lane = smem_u32(VT) +
        (unsigned)((((lid & 7) + ((lid & 16) ? 8 : 0)) * VT_STR
                    + ((lid & 8) ? 4 : 0)) * 4);

    float m0 = -INFINITY, m1 = -INFINITY, l0 = 0.f, l1 = 0.f;
    float o[16][4];
#pragma unroll
    for (int f = 0; f < 16; f++)
#pragma unroll
        for (int e = 0; e < 4; e++) o[f][e] = 0.f;

    const int src  = (lid & 0x1C) | (q_ >> 1);
    const int src2 = src + 2;
    const int par  = q_ & 1;

    const int nt = 2*qb + 2;
#pragma unroll 1
    for (int t = 0; t < nt; t++) {
        const int kb = t * 64;
        __syncthreads();
#pragma unroll
        for (int i = 0; i < 8; i++) {
            int pos = i*256 + tid;
            int row = pos >> 5;
            int c4  = (pos & 31) << 2;
            float4 v = *(const float4*)&kp[(size_t)(kb + row) * HD_ + c4];
            *(float4*)&Ks[row*QS_STR + c4] = tf32_4(v);
        }
#pragma unroll
        for (int i = 0; i < 32; i++) {
            int pos = i*256 + tid;
            int key = pos >> 7, hd = pos & 127;
            VT[hd*VT_STR + key] = to_tf32(vp[(size_t)(kb + key) * HD_ + hd]);
        }
        __syncthreads();

        float sc[8][4];
#pragma unroll
        for (int f = 0; f < 8; f++)
#pragma unroll
            for (int e = 0; e < 4; e++) sc[f][e] = 0.f;

#pragma unroll
        for (int kc = 0; kc < 16; kc++) {
            unsigned a0, a1, a2, a3;
            LDSM4(a0, a1, a2, a3, aq_base + (unsigned)(kc*32));
#pragma unroll
            for (int p = 0; p < 4; p++) {
                unsigned b0, b1, b2, b3;
                LDSM4(b0, b1, b2, b3,
                      ks_lane + (unsigned)((p*16*QS_STR + kc*8) * 4));
                MMAT32(sc[2*p],   a0, a1, a2, a3, b0, b1);
                MMAT32(sc[2*p+1], a0, a1, a2, a3, b2, b3);
            }
        }

        const bool maskt = (kb + 63 > q0);
        float mx0 = -INFINITY, mx1 = -INFINITY;
#pragma unroll
        for (int f = 0; f < 8; f++) {
            int cg = kb + f*8 + q_*2;
            float v0 = sc[f][0]*SCALE_, v1 = sc[f][1]*SCALE_;
            float v2 = sc[f][2]*SCALE_, v3 = sc[f][3]*SCALE_;
            if (maskt) {
                if (cg     > r0g)     v0 = -INFINITY;
                if (cg + 1 > r0g)     v1 = -INFINITY;
                if (cg     > r0g + 8) v2 = -INFINITY;
                if (cg + 1 > r0g + 8) v3 = -INFINITY;
            }
            sc[f][0] = v0; sc[f][1] = v1; sc[f][2] = v2; sc[f][3] = v3;
            mx0 = fmaxf(mx0, fmaxf(v0, v1));
            mx1 = fmaxf(mx1, fmaxf(v2, v3));
        }
        mx0 = fmaxf(mx0, __shfl_xor_sync(0xffffffffu, mx0, 1));
        mx0 = fmaxf(mx0, __shfl_xor_sync(0xffffffffu, mx0, 2));
        mx1 = fmaxf(mx1, __shfl_xor_sync(0xffffffffu, mx1, 1));
        mx1 = fmaxf(mx1, __shfl_xor_sync(0xffffffffu, mx1, 2));

        float mn0 = fmaxf(m0, mx0), mn1 = fmaxf(m1, mx1);
        float cr0 = __expf(m0 - mn0), cr1 = __expf(m1 - mn1);
        m0 = mn0; m1 = mn1;
#pragma unroll
        for (int f = 0; f < 16; f++) {
            o[f][0] *= cr0; o[f][1] *= cr0;
            o[f][2] *= cr1; o[f][3] *= cr1;
        }
        float s0 = 0.f, s1 = 0.f;
#pragma unroll
        for (int f = 0; f < 8; f++) {
            float p0 = __expf(sc[f][0] - mn0);
            float p1 = __expf(sc[f][1] - mn0);
            float p2 = __expf(sc[f][2] - mn1);
            float p3 = __expf(sc[f][3] - mn1);
            sc[f][0] = p0; sc[f][1] = p1; sc[f][2] = p2; sc[f][3] = p3;
            s0 += p0 + p1; s1 += p2 + p3;
        }
        l0 = l0*cr0 + s0; l1 = l1*cr1 + s1;

#pragma unroll
        for (int kc8 = 0; kc8 < 8; kc8++) {
            float e0a = __shfl_sync(0xffffffffu, sc[kc8][0], src);
            float e0b = __shfl_sync(0xffffffffu, sc[kc8][1], src);
            float e1a = __shfl_sync(0xffffffffu, sc[kc8][2], src);
            float e1b = __shfl_sync(0xffffffffu, sc[kc8][3], src);
            float e2a = __shfl_sync(0xffffffffu, sc[kc8][0], src2);
            float e2b = __shfl_sync(0xffffffffu, sc[kc8][1], src2);
            float e3a = __shfl_sync(0xffffffffu, sc[kc8][2], src2);
            float e3b = __shfl_sync(0xffffffffu, sc[kc8][3], src2);
            unsigned pa0 = to_tf32u(par ? e0b : e0a);
            unsigned pa1 = to_tf32u(par ? e1b : e1a);
            unsigned pa2 = to_tf32u(par ? e2b : e2a);
            unsigned pa3 = to_tf32u(par ? e3b : e3a);
#pragma unroll
            for (int g = 0; g < 8; g++) {
                unsigned v0, v1, v2, v3;
                LDSM4(v0, v1, v2, v3,
                      vt_lane + (unsigned)((g*16*VT_STR + kc8*8) * 4));
                MMAT32(o[2*g],   pa0, pa1, pa2, pa3, v0, v1);
                MMAT32(o[2*g+1], pa0, pa1, pa2, pa3, v2, v3);
            }
        }
    }

    l0 += __shfl_xor_sync(0xffffffffu, l0, 1);
    l0 += __shfl_xor_sync(0xffffffffu, l0, 2);
    l1 += __shfl_xor_sync(0xffffffffu, l1, 1);
    l1 += __shfl_xor_sync(0xffffffffu, l1, 2);
    float inv0 = 1.f / l0, inv1 = 1.f / l1;

    const int b = bh >> 4, h = bh & 15;
    const int row0 = q0 + wid*16 + a_;
    float* op0 = g_ao + ((size_t)(b*S_ + row0))     * D_ + h*HD_;
    float* op1 = g_ao + ((size_t)(b*S_ + row0 + 8)) * D_ + h*HD_;
#pragma unroll
    for (int f = 0; f < 16; f++) {
        int c = f*8 + q_*2;
        *(float2*)&op0[c] = make_float2(o[f][0]*inv0, o[f][1]*inv0);
        *(float2*)&op1[c] = make_float2(o[f][2]*inv1, o[f][3]*inv1);
    }
}

// =====================================================================
extern "C" void kernel_launch(void* const* d_in, const int* in_sizes, int n_in,
                              void* d_out, int out_size)
{
    (void)in_sizes; (void)n_in; (void)out_size;
    const float* x    = (const float*)d_in[0];
    // d_in[1] = mask: exactly causal, implemented analytically
    const float* cosT = (const float*)d_in[2];
    const float* sinT = (const float*)d_in[3];
    const float* Wq   = (const float*)d_in[4];
    const float* Wk   = (const float*)d_in[5];
    const float* Wv   = (const float*)d_in[6];
    const float* Wo   = (const float*)d_in[7];
    float* out = (float*)d_out;

    cudaFuncSetAttribute(gemm_tf32,
        cudaFuncAttributeMaxDynamicSharedMemorySize, GSMEM);
    cudaFuncSetAttribute(attn_tc,
        cudaFuncAttributeMaxDynamicSharedMemorySize, ATT2_SMEM);

    // 1) fused QKV projection (tf32 mma) -> [B,H,S,HD]
    dim3 gqkv(D_/128, M_/128, 3);
    gemm_tf32<<<gqkv, 512, GSMEM>>>(x, Wq, Wk, Wv, nullptr, 1);

    // 2) RoPE in place on q,k
    rope_kernel<<<(B_*H_*S_*64)/256, 256>>>(cosT, sinT);

    // 3) causal flash attention (tf32 tensor cores) -> g_ao [B,S,D]
    dim3 gatt(S_/128, B_*H_);
    attn_tc<<<gatt, 256, ATT2_SMEM>>>();

    // 4) output projection (tf32 mma)
    dim3 go(D_/128, M_/128, 1);
    gemm_tf32<<<go, 512, GSMEM>>>(nullptr, Wo, nullptr, nullptr, out, 0);
}